// round 1
// baseline (speedup 1.0000x reference)
#include <cuda_runtime.h>
#include <cuda_bf16.h>
#include <math.h>

// Problem sizes (fixed)
#define NN    8192
#define F_IN  512
#define H1D   256
#define H2D   128
#define WCATN 512   // H2*4

// ---------------- scratch (device globals; no allocation allowed) -----------
__device__ float g_T0[NN * H1D];       // x @ W1
__device__ float g_h1[NN * H1D];       // relu(adj @ T0)
__device__ float g_Wcat[H1D * WCATN];  // [W2|W3|W4|W5]
__device__ float g_T1[NN * WCATN];     // h1 @ Wcat
__device__ float g_Mb[NN * WCATN];     // adj @ T1  -> [mu|logvar|clz_mu|clz_logvar]
__device__ float g_uz[NN * H2D];       // updated_z
__device__ float g_prec[H2D];
__device__ float g_wmu[H2D];
__device__ float g_gmu[H2D];
__device__ float g_glv[H2D];
__device__ float g_crow[H2D];          // class_lat @ Wl[128:256] + bl

// ---------------- SGEMM: C[M,N] = A[M,K] @ B[K,N] (opt. B^T), fp32 ----------
// BM=BN=128, BK=16, 256 threads, 8x8 per-thread tile, register prefetch.
#define BMT 128
#define BNT 128
#define BKT 16
#define TT  8

template<bool TRANSB>
__global__ __launch_bounds__(256, 2)
void sgemm_k(const float* __restrict__ A, const float* __restrict__ B,
             float* __restrict__ C, int M, int N, int K, int epi)
{
    __shared__ float As[BKT][BMT + 4];
    __shared__ float Bs[BKT][BNT + 4];

    const int tid  = threadIdx.x;
    const int col0 = blockIdx.x * BNT;
    const int row0 = blockIdx.y * BMT;
    const int tx   = tid & 15;   // along N
    const int ty   = tid >> 4;   // along M

    float4 aPre[2], bPre[2];
    float acc[TT][TT];
#pragma unroll
    for (int i = 0; i < TT; i++)
#pragma unroll
        for (int j = 0; j < TT; j++) acc[i][j] = 0.0f;

    auto loadA = [&](int k0, float4* dst) {
#pragma unroll
        for (int r = 0; r < 2; r++) {
            int f  = tid + 256 * r;
            int ar = f >> 2;
            int ak = (f & 3) * 4;
            dst[r] = *(const float4*)(A + (size_t)(row0 + ar) * K + k0 + ak);
        }
    };
    auto loadB = [&](int k0, float4* dst) {
#pragma unroll
        for (int r = 0; r < 2; r++) {
            int f = tid + 256 * r;
            if (TRANSB) {
                int bn = f >> 2;
                int bk = (f & 3) * 4;
                dst[r] = *(const float4*)(B + (size_t)(col0 + bn) * K + k0 + bk);
            } else {
                int bk = f >> 5;
                int bn = (f & 31) * 4;
                dst[r] = *(const float4*)(B + (size_t)(k0 + bk) * N + col0 + bn);
            }
        }
    };
    auto storeA = [&](const float4* src) {
#pragma unroll
        for (int r = 0; r < 2; r++) {
            int f  = tid + 256 * r;
            int ar = f >> 2;
            int ak = (f & 3) * 4;
            As[ak + 0][ar] = src[r].x;
            As[ak + 1][ar] = src[r].y;
            As[ak + 2][ar] = src[r].z;
            As[ak + 3][ar] = src[r].w;
        }
    };
    auto storeB = [&](const float4* src) {
#pragma unroll
        for (int r = 0; r < 2; r++) {
            int f = tid + 256 * r;
            if (TRANSB) {
                int bn = f >> 2;
                int bk = (f & 3) * 4;
                Bs[bk + 0][bn] = src[r].x;
                Bs[bk + 1][bn] = src[r].y;
                Bs[bk + 2][bn] = src[r].z;
                Bs[bk + 3][bn] = src[r].w;
            } else {
                int bk = f >> 5;
                int bn = (f & 31) * 4;
                *(float4*)(&Bs[bk][bn]) = src[r];
            }
        }
    };

    loadA(0, aPre);
    loadB(0, bPre);
    storeA(aPre);
    storeB(bPre);
    __syncthreads();

    for (int k0 = BKT; k0 <= K; k0 += BKT) {
        const bool more = (k0 < K);
        if (more) { loadA(k0, aPre); loadB(k0, bPre); }
#pragma unroll
        for (int k = 0; k < BKT; k++) {
            float a[TT], b[TT];
#pragma unroll
            for (int i = 0; i < TT; i++) a[i] = As[k][ty * TT + i];
#pragma unroll
            for (int j = 0; j < TT; j++) b[j] = Bs[k][tx * TT + j];
#pragma unroll
            for (int i = 0; i < TT; i++)
#pragma unroll
                for (int j = 0; j < TT; j++)
                    acc[i][j] = fmaf(a[i], b[j], acc[i][j]);
        }
        __syncthreads();
        if (more) {
            storeA(aPre);
            storeB(bPre);
            __syncthreads();
        }
    }

    // epilogue: 0 none, 1 relu, 2 add broadcast row g_crow
#pragma unroll
    for (int i = 0; i < TT; i++) {
        const int row = row0 + ty * TT + i;
#pragma unroll
        for (int j = 0; j < TT; j += 4) {
            const int col = col0 + tx * TT + j;
            float4 v = make_float4(acc[i][j], acc[i][j + 1], acc[i][j + 2], acc[i][j + 3]);
            if (epi == 1) {
                v.x = fmaxf(v.x, 0.0f); v.y = fmaxf(v.y, 0.0f);
                v.z = fmaxf(v.z, 0.0f); v.w = fmaxf(v.w, 0.0f);
            } else if (epi == 2) {
                v.x += g_crow[col + 0]; v.y += g_crow[col + 1];
                v.z += g_crow[col + 2]; v.w += g_crow[col + 3];
            }
            *(float4*)(C + (size_t)row * N + col) = v;
        }
    }
}

// ---------------- elementwise / reduction kernels ---------------------------

// Build Wcat = [W2|W3|W4|W5]  (H1D x WCATN)
__global__ void k_wcat(const float* __restrict__ W2, const float* __restrict__ W3,
                       const float* __restrict__ W4, const float* __restrict__ W5,
                       float* __restrict__ Wcat)
{
    int idx = blockIdx.x * blockDim.x + threadIdx.x;
    if (idx >= H1D * WCATN) return;
    int r = idx / WCATN;
    int c = idx % WCATN;
    int sel = c >> 7;
    int cc = c & (H2D - 1);
    const float* W = (sel == 0) ? W2 : (sel == 1) ? W3 : (sel == 2) ? W4 : W5;
    Wcat[idx] = W[r * H2D + cc];
}

// z = eps_z * exp(logvar) + mu ; also emit mu, logvar
__global__ void k_z(const float* __restrict__ Mb, const float* __restrict__ eps_z,
                    float* __restrict__ out_z, float* __restrict__ out_mu,
                    float* __restrict__ out_lv)
{
    int idx = blockIdx.x * blockDim.x + threadIdx.x;
    if (idx >= NN * H2D) return;
    int i = idx >> 7;
    int j = idx & (H2D - 1);
    float mu = Mb[i * WCATN + j];
    float lv = Mb[i * WCATN + H2D + j];
    out_mu[idx] = mu;
    out_lv[idx] = lv;
    out_z[idx] = eps_z[idx] * expf(lv) + mu;
}

// per-column: prec[j] = sum_i 1/var, wmu[j] = sum_i clz_mu/var
__global__ void k_reduce(const float* __restrict__ Mb)
{
    __shared__ float s1[256];
    __shared__ float s2[256];
    int j = blockIdx.x;       // 0..127
    int t = threadIdx.x;      // 0..255
    float a = 0.0f, b = 0.0f;
    for (int i = t; i < NN; i += 256) {
        float cm = Mb[i * WCATN + 2 * H2D + j];
        float cl = Mb[i * WCATN + 3 * H2D + j];
        float var = expf(cl);
        if (var == 0.0f) var = 1e-6f;
        float inv = 1.0f / var;
        a += inv;
        b += cm * inv;
    }
    s1[t] = a; s2[t] = b;
    __syncthreads();
    for (int s = 128; s > 0; s >>= 1) {
        if (t < s) { s1[t] += s1[t + s]; s2[t] += s2[t + s]; }
        __syncthreads();
    }
    if (t == 0) { g_prec[j] = s1[0]; g_wmu[j] = s2[0]; }
}

// finalize group stats + class_lat, and const row = class_lat @ Wl[128:] + bl
__global__ void k_final(const float* __restrict__ eps_g, const float* __restrict__ Wl,
                        const float* __restrict__ bl)
{
    __shared__ float cl_sh[H2D];
    int j = threadIdx.x;  // 0..127
    float gvar = 1.0f / g_prec[j];
    float gmu = gvar * g_wmu[j];
    float gv = (gvar == 0.0f) ? 1e-6f : gvar;
    float glv = logf(gv);
    float cl = gmu + expf(0.5f * glv) * eps_g[j];
    g_gmu[j] = gmu;
    g_glv[j] = glv;
    cl_sh[j] = cl;
    __syncthreads();
    float s = bl[j];
#pragma unroll 8
    for (int k = 0; k < H2D; k++)
        s = fmaf(cl_sh[k], Wl[(H2D + k) * H2D + j], s);
    g_crow[j] = s;
}

// broadcast grouped_mu / grouped_logvar to [N, H2]
__global__ void k_bcast(float* __restrict__ out_gmu, float* __restrict__ out_glv)
{
    int idx = blockIdx.x * blockDim.x + threadIdx.x;
    if (idx >= NN * H2D) return;
    int j = idx & (H2D - 1);
    out_gmu[idx] = g_gmu[j];
    out_glv[idx] = g_glv[j];
}

// ---------------- launch ----------------------------------------------------
extern "C" void kernel_launch(void* const* d_in, const int* in_sizes, int n_in,
                              void* d_out, int out_size)
{
    const float* x     = (const float*)d_in[0];
    const float* adj   = (const float*)d_in[1];
    const float* W1    = (const float*)d_in[2];
    const float* W2    = (const float*)d_in[3];
    const float* W3    = (const float*)d_in[4];
    const float* W4    = (const float*)d_in[5];
    const float* W5    = (const float*)d_in[6];
    const float* Wl    = (const float*)d_in[7];
    const float* bl    = (const float*)d_in[8];
    const float* eps_z = (const float*)d_in[9];
    const float* eps_g = (const float*)d_in[10];
    // d_in[11] = batch (all zeros; single group) -- unused

    float* out = (float*)d_out;
    float* out_recon = out;                                  // 8192*8192
    float* out_z     = out + (size_t)NN * NN;                // 8192*128
    float* out_mu    = out_z  + (size_t)NN * H2D;
    float* out_lv    = out_mu + (size_t)NN * H2D;
    float* out_gmu   = out_lv + (size_t)NN * H2D;
    float* out_glv   = out_gmu + (size_t)NN * H2D;

    float *T0, *h1, *Wcat, *T1, *Mb, *uz;
    cudaGetSymbolAddress((void**)&T0,   g_T0);
    cudaGetSymbolAddress((void**)&h1,   g_h1);
    cudaGetSymbolAddress((void**)&Wcat, g_Wcat);
    cudaGetSymbolAddress((void**)&T1,   g_T1);
    cudaGetSymbolAddress((void**)&Mb,   g_Mb);
    cudaGetSymbolAddress((void**)&uz,   g_uz);

    const dim3 blk(256);

    // T0 = x @ W1                        [8192,256] K=512
    sgemm_k<false><<<dim3(H1D / BNT, NN / BMT), blk>>>(x, W1, T0, NN, H1D, F_IN, 0);
    // Wcat = [W2|W3|W4|W5]
    k_wcat<<<(H1D * WCATN + 255) / 256, 256>>>(W2, W3, W4, W5, Wcat);
    // h1 = relu(adj @ T0)                [8192,256] K=8192
    sgemm_k<false><<<dim3(H1D / BNT, NN / BMT), blk>>>(adj, T0, h1, NN, H1D, NN, 1);
    // T1 = h1 @ Wcat                     [8192,512] K=256
    sgemm_k<false><<<dim3(WCATN / BNT, NN / BMT), blk>>>(h1, Wcat, T1, NN, WCATN, H1D, 0);
    // Mb = adj @ T1                      [8192,512] K=8192
    sgemm_k<false><<<dim3(WCATN / BNT, NN / BMT), blk>>>(adj, T1, Mb, NN, WCATN, NN, 0);
    // z / mu / logvar
    k_z<<<(NN * H2D + 255) / 256, 256>>>(Mb, eps_z, out_z, out_mu, out_lv);
    // group evidence
    k_reduce<<<H2D, 256>>>(Mb);
    k_final<<<1, H2D>>>(eps_g, Wl, bl);
    k_bcast<<<(NN * H2D + 255) / 256, 256>>>(out_gmu, out_glv);
    // uz = z @ Wl[0:128] + crow          [8192,128] K=128
    sgemm_k<false><<<dim3(H2D / BNT, NN / BMT), blk>>>(out_z, Wl, uz, NN, H2D, H2D, 2);
    // adj_recon = uz @ uz^T              [8192,8192] K=128
    sgemm_k<true><<<dim3(NN / BNT, NN / BMT), blk>>>(uz, uz, out_recon, NN, NN, H2D, 0);
}

// round 4
// speedup vs baseline: 2.4713x; 2.4713x over previous
#include <cuda_runtime.h>
#include <cstdint>
#include <math.h>

// Problem sizes (fixed)
#define NN    8192
#define F_IN  512
#define H1D   256
#define H2D   128
#define WCATN 512   // 4*H2

// ---------------- scratch (device globals; no allocation allowed) -----------
__device__ float g_T0t[H1D * NN];      // (x @ W1)^T          [256][8192]
__device__ float g_h1[NN * H1D];       // relu(adj @ T0)      [8192][256]
__device__ float g_W1t[H1D * F_IN];    // W1^T                [256][512]
__device__ float g_Wcatt[WCATN * H1D]; // [W2|W3|W4|W5]^T     [512][256]
__device__ float g_T1t[WCATN * NN];    // (h1 @ Wcat)^T       [512][8192]
__device__ float g_Mb[NN * WCATN];     // adj @ T1            [8192][512]
__device__ float g_Wlt[H2D * H2D];     // Wl[0:128,:]^T       [128][128]
__device__ float g_uz[NN * H2D];       // updated_z           [8192][128]
__device__ float g_prec[H2D];
__device__ float g_wmu[H2D];
__device__ float g_gmu[H2D];
__device__ float g_glv[H2D];
__device__ float g_crow[H2D];          // class_lat @ Wl[128:256] + bl

// ---------------- common tile config ----------------------------------------
#define TILE       128
#define BKC        32
#define SM_HDR     1024
#define TILE_BYTES (TILE * 128)          // 16 KB per sub-tile (128 rows x 128B)
#define BUF_BYTES  (4 * TILE_BYTES)      // Ahi Alo Bhi Blo
#define SMEM_TOT   (SM_HDR + 2 * BUF_BYTES)

#if defined(__CUDA_ARCH_FEAT_SM103_ALL) || defined(__CUDA_ARCH_FEAT_SM100_ALL)
#define HAVE_TCGEN05 1
#else
#define HAVE_TCGEN05 0
#endif

// ---------------- ptx helpers (only used on the 103a path) ------------------
__device__ __forceinline__ uint32_t elect_one_pred() {
    uint32_t pred;
    asm volatile(
        "{\n\t.reg .pred p;\n\telect.sync _|p, 0xFFFFFFFF;\n\tselp.b32 %0, 1, 0, p;\n\t}"
        : "=r"(pred));
    return pred;
}
__device__ __forceinline__ uint32_t smem_to_u32(const void* smem_ptr) {
    uint32_t addr;
    asm("{ .reg .u64 tmp; cvta.to.shared.u64 tmp, %1; cvt.u32.u64 %0, tmp; }"
        : "=r"(addr) : "l"(smem_ptr));
    return addr;
}

#if HAVE_TCGEN05

#define MBARRIER_INIT(mbar, count) \
    asm volatile("mbarrier.init.shared.b64 [%0], %1;" \
        :: "r"((uint32_t)(mbar)), "r"((uint32_t)(count)) : "memory")

#define MBARRIER_WAIT_PARITY(mbar_smem_addr, phase_parity) do { \
    uint32_t _mbar = (uint32_t)(mbar_smem_addr); \
    uint32_t _parity = (uint32_t)(phase_parity); \
    uint32_t _done; \
    asm volatile( \
        "{\n\t.reg .pred p;\n\t" \
        "mbarrier.try_wait.parity.acquire.cta.shared::cta.b64 p, [%1], %2;\n\t" \
        "selp.b32 %0, 1, 0, p;\n\t}" \
        : "=r"(_done) : "r"(_mbar), "r"(_parity) : "memory"); \
    if (!_done) { \
        asm volatile( \
            "{\n\t.reg .pred P1;\n\t" \
            "WAIT_LOOP_%=:\n\t" \
            "mbarrier.try_wait.parity.acquire.cta.shared::cta.b64 P1, [%0], %1, 0x989680;\n\t" \
            "@P1 bra.uni WAIT_DONE_%=;\n\t" \
            "bra.uni WAIT_LOOP_%=;\n\t" \
            "WAIT_DONE_%=:\n\t}" \
            :: "r"(_mbar), "r"(_parity) : "memory"); \
    } \
} while(0)

#define TCGEN05_ALLOC(smem_result_addr, nCols) \
    asm volatile("tcgen05.alloc.cta_group::1.sync.aligned.shared::cta.b32 [%0], %1;" \
        :: "r"((uint32_t)(smem_result_addr)), "r"((uint32_t)(nCols)) : "memory")
#define TCGEN05_DEALLOC(tmem_addr, nCols) \
    asm volatile("tcgen05.dealloc.cta_group::1.sync.aligned.b32 %0, %1;" \
        :: "r"(tmem_addr), "r"((uint32_t)(nCols)))
#define TCGEN05_RELINQUISH() \
    asm volatile("tcgen05.relinquish_alloc_permit.cta_group::1.sync.aligned;")
#define TCGEN05_COMMIT(mbar_smem_addr) \
    asm volatile("tcgen05.commit.cta_group::1.mbarrier::arrive::one.shared::cluster.b64 [%0];" \
        :: "r"((uint32_t)(mbar_smem_addr)) : "memory")
#define TCGEN05_WAIT_LD() \
    asm volatile("tcgen05.wait::ld.sync.aligned;" ::: "memory")
#define TCGEN05_FENCE_AFTER() \
    asm volatile("tcgen05.fence::after_thread_sync;" ::: "memory")
#define FENCE_ASYNC_SHARED() \
    asm volatile("fence.proxy.async.shared::cta;" ::: "memory")

#define TCGEN05_LD_32X32B_X32(r, tmem_addr) \
    asm volatile( \
        "tcgen05.ld.sync.aligned.32x32b.x32.b32 " \
        "{%0, %1, %2, %3, %4, %5, %6, %7, " \
        " %8, %9, %10, %11, %12, %13, %14, %15, " \
        " %16, %17, %18, %19, %20, %21, %22, %23, " \
        " %24, %25, %26, %27, %28, %29, %30, %31}, [%32];" \
        : "=r"((r)[0]),  "=r"((r)[1]),  "=r"((r)[2]),  "=r"((r)[3]), \
          "=r"((r)[4]),  "=r"((r)[5]),  "=r"((r)[6]),  "=r"((r)[7]), \
          "=r"((r)[8]),  "=r"((r)[9]),  "=r"((r)[10]), "=r"((r)[11]), \
          "=r"((r)[12]), "=r"((r)[13]), "=r"((r)[14]), "=r"((r)[15]), \
          "=r"((r)[16]), "=r"((r)[17]), "=r"((r)[18]), "=r"((r)[19]), \
          "=r"((r)[20]), "=r"((r)[21]), "=r"((r)[22]), "=r"((r)[23]), \
          "=r"((r)[24]), "=r"((r)[25]), "=r"((r)[26]), "=r"((r)[27]), \
          "=r"((r)[28]), "=r"((r)[29]), "=r"((r)[30]), "=r"((r)[31]) \
        : "r"(tmem_addr))

// SW128 K-major smem descriptor base: layout=SW128, version=1, SBO=64, LBO=1
static constexpr uint64_t SMEM_DESC_BASE_SW128 =
    (uint64_t(2)  << 61) | (uint64_t(1) << 46) | (uint64_t(64) << 32) | (uint64_t(1) << 16);
#define MAKE_SMEM_DESC(base_addr) \
    (SMEM_DESC_BASE_SW128 | ((uint64_t)((base_addr) >> 4) & 0x3FFF))

// idesc: c=F32(1@4), a=TF32(2@7), b=TF32(2@10), N>>3 @17, M>>4 @24
static constexpr uint32_t IDESC_TF32 =
    (1u << 4) | (2u << 7) | (2u << 10) | ((TILE / 8) << 17) | ((TILE / 16) << 24);

__device__ __forceinline__ void mma_tf32(uint32_t d, uint64_t ad, uint64_t bd, uint32_t en) {
    asm volatile(
        "{\n\t.reg .pred p;\n\tsetp.ne.u32 p, %4, 0;\n\t"
        "tcgen05.mma.cta_group::1.kind::tf32 [%0], %1, %2, %3, {%5,%5,%5,%5}, p;\n\t}"
        :: "r"(d), "l"(ad), "l"(bd), "r"(IDESC_TF32), "r"(en), "r"(0u) : "memory");
}

// stage one 128x32 fp32 tile into hi/lo tf32-split SW128-swizzled smem tiles
__device__ __forceinline__ void stage_tile(const float* __restrict__ src, int ld,
                                           int rowbase, int k0,
                                           char* sm_hi, char* sm_lo, int tid)
{
#pragma unroll
    for (int it = 0; it < 4; ++it) {
        int f = tid + 256 * it;
        int r = f >> 3;
        int c = f & 7;
        const float4 v = *(const float4*)(src + (size_t)(rowbase + r) * ld + k0 + c * 4);
        uint32_t off = (uint32_t)(r * 128 + c * 16);
        uint32_t sw = off ^ ((off >> 3) & 0x70);
        float4 h, l;
        h.x = __uint_as_float(__float_as_uint(v.x) & 0xFFFFE000u); l.x = v.x - h.x;
        h.y = __uint_as_float(__float_as_uint(v.y) & 0xFFFFE000u); l.y = v.y - h.y;
        h.z = __uint_as_float(__float_as_uint(v.z) & 0xFFFFE000u); l.z = v.z - h.z;
        h.w = __uint_as_float(__float_as_uint(v.w) & 0xFFFFE000u); l.w = v.w - h.w;
        *(float4*)(sm_hi + sw) = h;
        *(float4*)(sm_lo + sw) = l;
    }
}
#endif  // HAVE_TCGEN05

// ---------------- GEMM: C = A[M,K] @ Bt[N,K]^T (fp32 in/out) ----------------
// epi: 0 none, 1 relu, 2 add broadcast row g_crow
// transC: 0 -> C[row*ldc+col]; 1 -> C[col*ldc+row]
__global__ void __launch_bounds__(256, 1)
gemm_any(const float* __restrict__ A, int lda,
         const float* __restrict__ Bt, int ldb,
         float* __restrict__ C, int ldc, int K, int epi, int transC)
{
    extern __shared__ char smem[];
    const int tid = threadIdx.x;
    const int col0 = blockIdx.x * TILE;
    const int row0 = blockIdx.y * TILE;

#if HAVE_TCGEN05
    // ---------------- tcgen05 3xTF32 path ----------------
    const uint32_t smem_base = smem_to_u32(smem);
    const int wid = tid >> 5;
    const int lid = tid & 31;

    if (wid == 0) TCGEN05_ALLOC(smem_base + 0, 128);
    if (tid == 0) {
        MBARRIER_INIT(smem_base + 8, 1);    // mbar for buffer 0
        MBARRIER_INIT(smem_base + 16, 1);   // mbar for buffer 1
    }
    __syncthreads();
    uint32_t tmem;
    asm volatile("ld.shared.b32 %0, [%1];" : "=r"(tmem) : "r"(smem_base));

    char* bufs = smem + SM_HDR;   // per buf: [Ahi][Alo][Bhi][Blo]

    stage_tile(A,  lda, row0, 0, bufs + 0 * TILE_BYTES, bufs + 1 * TILE_BYTES, tid);
    stage_tile(Bt, ldb, col0, 0, bufs + 2 * TILE_BYTES, bufs + 3 * TILE_BYTES, tid);
    FENCE_ASYNC_SHARED();
    __syncthreads();

    const int nch = K / BKC;
    for (int c = 0; c < nch; ++c) {
        const int buf = c & 1;
        // issue MMAs for chunk c on buffer buf; commit -> mbar[buf]
        if (wid == 0 && elect_one_pred()) {
            uint64_t ah = MAKE_SMEM_DESC(smem_base + SM_HDR + buf * BUF_BYTES);
            uint64_t al = ah + (TILE_BYTES >> 4);
            uint64_t bh = ah + 2 * (TILE_BYTES >> 4);
            uint64_t bl = ah + 3 * (TILE_BYTES >> 4);
            uint32_t en = (c > 0) ? 1u : 0u;
#pragma unroll
            for (int s = 0; s < 4; ++s) {   // 4 k-steps of 8 (32B = 2 desc units)
                mma_tf32(tmem, ah + 2 * s, bh + 2 * s, en); en = 1u;
                mma_tf32(tmem, ah + 2 * s, bl + 2 * s, 1u);
                mma_tf32(tmem, al + 2 * s, bh + 2 * s, 1u);
            }
            TCGEN05_COMMIT(smem_base + 8 + 8 * buf);
        }
        if (c + 1 < nch) {
            // buffer buf^1 was last used by chunk c-1 (its ((c-1)>>1)-th commit).
            // That mbar gets no further commits until next iteration -> no phase lap.
            if (c >= 1) MBARRIER_WAIT_PARITY(smem_base + 8 + 8 * (buf ^ 1), ((c - 1) >> 1) & 1);
            char* nb = bufs + (buf ^ 1) * BUF_BYTES;
            stage_tile(A,  lda, row0, (c + 1) * BKC, nb + 0 * TILE_BYTES, nb + 1 * TILE_BYTES, tid);
            stage_tile(Bt, ldb, col0, (c + 1) * BKC, nb + 2 * TILE_BYTES, nb + 3 * TILE_BYTES, tid);
            FENCE_ASYNC_SHARED();
        }
        __syncthreads();
    }
    // wait for the final chunk's MMA (serialized accumulator => all prior done)
    MBARRIER_WAIT_PARITY(smem_base + 8 + 8 * ((nch - 1) & 1), ((nch - 1) >> 1) & 1);
    TCGEN05_FENCE_AFTER();

    if (wid < 4) {
        const int row = row0 + wid * 32 + lid;
#pragma unroll
        for (int g = 0; g < 4; ++g) {
            uint32_t r[32];
            TCGEN05_LD_32X32B_X32(r, tmem + g * 32);
            TCGEN05_WAIT_LD();
            if (!transC) {
#pragma unroll
                for (int j = 0; j < 32; j += 4) {
                    const int col = col0 + g * 32 + j;
                    float4 v;
                    v.x = __uint_as_float(r[j + 0]);
                    v.y = __uint_as_float(r[j + 1]);
                    v.z = __uint_as_float(r[j + 2]);
                    v.w = __uint_as_float(r[j + 3]);
                    if (epi == 1) {
                        v.x = fmaxf(v.x, 0.0f); v.y = fmaxf(v.y, 0.0f);
                        v.z = fmaxf(v.z, 0.0f); v.w = fmaxf(v.w, 0.0f);
                    } else if (epi == 2) {
                        v.x += g_crow[col + 0]; v.y += g_crow[col + 1];
                        v.z += g_crow[col + 2]; v.w += g_crow[col + 3];
                    }
                    *(float4*)(C + (size_t)row * ldc + col) = v;
                }
            } else {
#pragma unroll
                for (int j = 0; j < 32; ++j) {
                    const int col = col0 + g * 32 + j;
                    C[(size_t)col * ldc + row] = __uint_as_float(r[j]);
                }
            }
        }
    }
    __syncthreads();
    if (tid == 0) {
        asm volatile("mbarrier.inval.shared.b64 [%0];" :: "r"(smem_base + 8) : "memory");
        asm volatile("mbarrier.inval.shared.b64 [%0];" :: "r"(smem_base + 16) : "memory");
    }
    __syncthreads();
    if (wid == 0) {
        TCGEN05_RELINQUISH();
        TCGEN05_DEALLOC(tmem, 128);
    }

#else
    // ---------------- FFMA fallback (validated R1 SGEMM, Bt layout) ---------
    const int BKT = 16, TT = 8;
    float* As = (float*)smem;             // [16][132]
    float* Bs = As + BKT * (TILE + 4);    // [16][132]
    const int tx = tid & 15;   // along N
    const int ty = tid >> 4;   // along M

    float4 aPre[2], bPre[2];
    float acc[8][8];
#pragma unroll
    for (int i = 0; i < TT; i++)
#pragma unroll
        for (int j = 0; j < TT; j++) acc[i][j] = 0.0f;

    auto loadA = [&](int k0, float4* dst) {
#pragma unroll
        for (int r = 0; r < 2; r++) {
            int f = tid + 256 * r;
            int ar = f >> 2;
            int ak = (f & 3) * 4;
            dst[r] = *(const float4*)(A + (size_t)(row0 + ar) * lda + k0 + ak);
        }
    };
    auto loadB = [&](int k0, float4* dst) {
#pragma unroll
        for (int r = 0; r < 2; r++) {
            int f = tid + 256 * r;
            int bn = f >> 2;
            int bk = (f & 3) * 4;
            dst[r] = *(const float4*)(Bt + (size_t)(col0 + bn) * ldb + k0 + bk);
        }
    };
    auto storeA = [&](const float4* src) {
#pragma unroll
        for (int r = 0; r < 2; r++) {
            int f = tid + 256 * r;
            int ar = f >> 2;
            int ak = (f & 3) * 4;
            As[(ak + 0) * (TILE + 4) + ar] = src[r].x;
            As[(ak + 1) * (TILE + 4) + ar] = src[r].y;
            As[(ak + 2) * (TILE + 4) + ar] = src[r].z;
            As[(ak + 3) * (TILE + 4) + ar] = src[r].w;
        }
    };
    auto storeB = [&](const float4* src) {
#pragma unroll
        for (int r = 0; r < 2; r++) {
            int f = tid + 256 * r;
            int bn = f >> 2;
            int bk = (f & 3) * 4;
            Bs[(bk + 0) * (TILE + 4) + bn] = src[r].x;
            Bs[(bk + 1) * (TILE + 4) + bn] = src[r].y;
            Bs[(bk + 2) * (TILE + 4) + bn] = src[r].z;
            Bs[(bk + 3) * (TILE + 4) + bn] = src[r].w;
        }
    };

    loadA(0, aPre);
    loadB(0, bPre);
    storeA(aPre);
    storeB(bPre);
    __syncthreads();

    for (int k0 = BKT; k0 <= K; k0 += BKT) {
        const bool more = (k0 < K);
        if (more) { loadA(k0, aPre); loadB(k0, bPre); }
#pragma unroll
        for (int k = 0; k < BKT; k++) {
            float a[8], b[8];
#pragma unroll
            for (int i = 0; i < TT; i++) a[i] = As[k * (TILE + 4) + ty * TT + i];
#pragma unroll
            for (int j = 0; j < TT; j++) b[j] = Bs[k * (TILE + 4) + tx * TT + j];
#pragma unroll
            for (int i = 0; i < TT; i++)
#pragma unroll
                for (int j = 0; j < TT; j++)
                    acc[i][j] = fmaf(a[i], b[j], acc[i][j]);
        }
        __syncthreads();
        if (more) {
            storeA(aPre);
            storeB(bPre);
            __syncthreads();
        }
    }

#pragma unroll
    for (int i = 0; i < TT; i++) {
        const int row = row0 + ty * TT + i;
#pragma unroll
        for (int j = 0; j < TT; j += 4) {
            const int col = col0 + tx * TT + j;
            float4 v = make_float4(acc[i][j], acc[i][j + 1], acc[i][j + 2], acc[i][j + 3]);
            if (epi == 1) {
                v.x = fmaxf(v.x, 0.0f); v.y = fmaxf(v.y, 0.0f);
                v.z = fmaxf(v.z, 0.0f); v.w = fmaxf(v.w, 0.0f);
            } else if (epi == 2) {
                v.x += g_crow[col + 0]; v.y += g_crow[col + 1];
                v.z += g_crow[col + 2]; v.w += g_crow[col + 3];
            }
            if (!transC) {
                *(float4*)(C + (size_t)row * ldc + col) = v;
            } else {
                C[(size_t)(col + 0) * ldc + row] = v.x;
                C[(size_t)(col + 1) * ldc + row] = v.y;
                C[(size_t)(col + 2) * ldc + row] = v.z;
                C[(size_t)(col + 3) * ldc + row] = v.w;
            }
        }
    }
#endif
}

// ---------------- small transpose / elementwise kernels ---------------------
__global__ void k_w1t(const float* __restrict__ W1, float* __restrict__ W1t) {
    int idx = blockIdx.x * blockDim.x + threadIdx.x;
    if (idx >= H1D * F_IN) return;
    int n = idx / F_IN, k = idx % F_IN;
    W1t[idx] = W1[k * H1D + n];
}
__global__ void k_wcatt(const float* __restrict__ W2, const float* __restrict__ W3,
                        const float* __restrict__ W4, const float* __restrict__ W5,
                        float* __restrict__ Wcatt) {
    int idx = blockIdx.x * blockDim.x + threadIdx.x;
    if (idx >= WCATN * H1D) return;
    int n = idx / H1D, k = idx % H1D;
    int sel = n >> 7, nn = n & (H2D - 1);
    const float* W = (sel == 0) ? W2 : (sel == 1) ? W3 : (sel == 2) ? W4 : W5;
    Wcatt[idx] = W[k * H2D + nn];
}
__global__ void k_wlt(const float* __restrict__ Wl, float* __restrict__ Wlt) {
    int idx = blockIdx.x * blockDim.x + threadIdx.x;
    if (idx >= H2D * H2D) return;
    int n = idx / H2D, k = idx % H2D;
    Wlt[idx] = Wl[k * H2D + n];  // top half of Wl
}

__global__ void k_z(const float* __restrict__ Mb, const float* __restrict__ eps_z,
                    float* __restrict__ out_z, float* __restrict__ out_mu,
                    float* __restrict__ out_lv) {
    int idx = blockIdx.x * blockDim.x + threadIdx.x;
    if (idx >= NN * H2D) return;
    int i = idx >> 7, j = idx & (H2D - 1);
    float mu = Mb[i * WCATN + j];
    float lv = Mb[i * WCATN + H2D + j];
    out_mu[idx] = mu;
    out_lv[idx] = lv;
    out_z[idx] = eps_z[idx] * expf(lv) + mu;
}

__global__ void k_reduce(const float* __restrict__ Mb) {
    __shared__ float s1[256];
    __shared__ float s2[256];
    int j = blockIdx.x, t = threadIdx.x;
    float a = 0.0f, b = 0.0f;
    for (int i = t; i < NN; i += 256) {
        float cm = Mb[i * WCATN + 2 * H2D + j];
        float cl = Mb[i * WCATN + 3 * H2D + j];
        float var = expf(cl);
        if (var == 0.0f) var = 1e-6f;
        float inv = 1.0f / var;
        a += inv;
        b += cm * inv;
    }
    s1[t] = a; s2[t] = b;
    __syncthreads();
    for (int s = 128; s > 0; s >>= 1) {
        if (t < s) { s1[t] += s1[t + s]; s2[t] += s2[t + s]; }
        __syncthreads();
    }
    if (t == 0) { g_prec[j] = s1[0]; g_wmu[j] = s2[0]; }
}

__global__ void k_final(const float* __restrict__ eps_g, const float* __restrict__ Wl,
                        const float* __restrict__ bl) {
    __shared__ float cl_sh[H2D];
    int j = threadIdx.x;
    float gvar = 1.0f / g_prec[j];
    float gmu = gvar * g_wmu[j];
    float gv = (gvar == 0.0f) ? 1e-6f : gvar;
    float glv = logf(gv);
    float cl = gmu + expf(0.5f * glv) * eps_g[j];
    g_gmu[j] = gmu;
    g_glv[j] = glv;
    cl_sh[j] = cl;
    __syncthreads();
    float s = bl[j];
#pragma unroll 8
    for (int k = 0; k < H2D; k++)
        s = fmaf(cl_sh[k], Wl[(H2D + k) * H2D + j], s);
    g_crow[j] = s;
}

__global__ void k_bcast(float* __restrict__ out_gmu, float* __restrict__ out_glv) {
    int idx = blockIdx.x * blockDim.x + threadIdx.x;
    if (idx >= NN * H2D) return;
    int j = idx & (H2D - 1);
    out_gmu[idx] = g_gmu[j];
    out_glv[idx] = g_glv[j];
}

// ---------------- launch ----------------------------------------------------
extern "C" void kernel_launch(void* const* d_in, const int* in_sizes, int n_in,
                              void* d_out, int out_size)
{
    const float* x     = (const float*)d_in[0];
    const float* adj   = (const float*)d_in[1];
    const float* W1    = (const float*)d_in[2];
    const float* W2    = (const float*)d_in[3];
    const float* W3    = (const float*)d_in[4];
    const float* W4    = (const float*)d_in[5];
    const float* W5    = (const float*)d_in[6];
    const float* Wl    = (const float*)d_in[7];
    const float* bl    = (const float*)d_in[8];
    const float* eps_z = (const float*)d_in[9];
    const float* eps_g = (const float*)d_in[10];

    float* out = (float*)d_out;
    float* out_recon = out;
    float* out_z     = out + (size_t)NN * NN;
    float* out_mu    = out_z  + (size_t)NN * H2D;
    float* out_lv    = out_mu + (size_t)NN * H2D;
    float* out_gmu   = out_lv + (size_t)NN * H2D;
    float* out_glv   = out_gmu + (size_t)NN * H2D;

    float *T0t, *h1, *W1t, *Wcatt, *T1t, *Mb, *Wlt, *uz;
    cudaGetSymbolAddress((void**)&T0t,   g_T0t);
    cudaGetSymbolAddress((void**)&h1,    g_h1);
    cudaGetSymbolAddress((void**)&W1t,   g_W1t);
    cudaGetSymbolAddress((void**)&Wcatt, g_Wcatt);
    cudaGetSymbolAddress((void**)&T1t,   g_T1t);
    cudaGetSymbolAddress((void**)&Mb,    g_Mb);
    cudaGetSymbolAddress((void**)&Wlt,   g_Wlt);
    cudaGetSymbolAddress((void**)&uz,    g_uz);

    cudaFuncSetAttribute(gemm_any, cudaFuncAttributeMaxDynamicSharedMemorySize, SMEM_TOT);

    // weight transposes (small)
    k_w1t  <<<(H1D * F_IN + 255) / 256, 256>>>(W1, W1t);
    k_wcatt<<<(WCATN * H1D + 255) / 256, 256>>>(W2, W3, W4, W5, Wcatt);
    k_wlt  <<<(H2D * H2D + 255) / 256, 256>>>(Wl, Wlt);

    // G1: T0t = (x @ W1)^T        M=8192 N=256 K=512
    gemm_any<<<dim3(H1D / TILE, NN / TILE), 256, SMEM_TOT>>>(x, F_IN, W1t, F_IN, T0t, NN, F_IN, 0, 1);
    // G2: h1 = relu(adj @ T0)     M=8192 N=256 K=8192
    gemm_any<<<dim3(H1D / TILE, NN / TILE), 256, SMEM_TOT>>>(adj, NN, T0t, NN, h1, H1D, NN, 1, 0);
    // G3: T1t = (h1 @ Wcat)^T     M=8192 N=512 K=256
    gemm_any<<<dim3(WCATN / TILE, NN / TILE), 256, SMEM_TOT>>>(h1, H1D, Wcatt, H1D, T1t, NN, H1D, 0, 1);
    // G4: Mb = adj @ T1           M=8192 N=512 K=8192
    gemm_any<<<dim3(WCATN / TILE, NN / TILE), 256, SMEM_TOT>>>(adj, NN, T1t, NN, Mb, WCATN, NN, 0, 0);

    // z / mu / logvar + group evidence
    k_z     <<<(NN * H2D + 255) / 256, 256>>>(Mb, eps_z, out_z, out_mu, out_lv);
    k_reduce<<<H2D, 256>>>(Mb);
    k_final <<<1, H2D>>>(eps_g, Wl, bl);
    k_bcast <<<(NN * H2D + 255) / 256, 256>>>(out_gmu, out_glv);

    // G5: uz = z @ Wl_top + crow  M=8192 N=128 K=128
    gemm_any<<<dim3(1, NN / TILE), 256, SMEM_TOT>>>(out_z, H2D, Wlt, H2D, uz, H2D, H2D, 2, 0);
    // G6: recon = uz @ uz^T       M=8192 N=8192 K=128
    gemm_any<<<dim3(NN / TILE, NN / TILE), 256, SMEM_TOT>>>(uz, H2D, uz, H2D, out_recon, NN, H2D, 0, 0);
}

// round 6
// speedup vs baseline: 2.5796x; 1.0438x over previous
#include <cuda_runtime.h>
#include <cstdint>
#include <math.h>

// Problem sizes (fixed)
#define NN    8192
#define F_IN  512
#define H1D   256
#define H2D   128
#define WCATN 512   // 4*H2

// ---------------- scratch (device globals; no allocation allowed) -----------
__device__ float g_T0t[H1D * NN];      // (x @ W1)^T          [256][8192]
__device__ float g_h1[NN * H1D];       // relu(adj @ T0)      [8192][256]
__device__ float g_W1t[H1D * F_IN];    // W1^T                [256][512]
__device__ float g_Wcatt[WCATN * H1D]; // [W2|W3|W4|W5]^T     [512][256]
__device__ float g_T1t[WCATN * NN];    // (h1 @ Wcat)^T       [512][8192]
__device__ float g_Mb[NN * WCATN];     // adj @ T1            [8192][512]
__device__ float g_Wlt[H2D * H2D];     // Wl[0:128,:]^T       [128][128]
__device__ float g_uz[NN * H2D];       // updated_z           [8192][128]
__device__ float g_prec[H2D];
__device__ float g_wmu[H2D];
__device__ float g_gmu[H2D];
__device__ float g_glv[H2D];
__device__ float g_crow[H2D];          // class_lat @ Wl[128:256] + bl

// ---------------- common tile config ----------------------------------------
#define TILE       128
#define BKC        32
#define NTHR       512
#define SM_HDR     1024
#define TILE_BYTES (TILE * 128)          // 16 KB per sub-tile (128 rows x 128B)
#define BUF_BYTES  (4 * TILE_BYTES)      // Ahi Alo Bhi Blo
#define SMEM_TOT   (SM_HDR + 2 * BUF_BYTES)

#if defined(__CUDA_ARCH_FEAT_SM103_ALL) || defined(__CUDA_ARCH_FEAT_SM100_ALL)
#define HAVE_TCGEN05 1
#else
#define HAVE_TCGEN05 0
#endif

// ---------------- ptx helpers (only used on the 103a path) ------------------
__device__ __forceinline__ uint32_t elect_one_pred() {
    uint32_t pred;
    asm volatile(
        "{\n\t.reg .pred p;\n\telect.sync _|p, 0xFFFFFFFF;\n\tselp.b32 %0, 1, 0, p;\n\t}"
        : "=r"(pred));
    return pred;
}
__device__ __forceinline__ uint32_t smem_to_u32(const void* smem_ptr) {
    uint32_t addr;
    asm("{ .reg .u64 tmp; cvta.to.shared.u64 tmp, %1; cvt.u32.u64 %0, tmp; }"
        : "=r"(addr) : "l"(smem_ptr));
    return addr;
}

#if HAVE_TCGEN05

#define MBARRIER_INIT(mbar, count) \
    asm volatile("mbarrier.init.shared.b64 [%0], %1;" \
        :: "r"((uint32_t)(mbar)), "r"((uint32_t)(count)) : "memory")

#define MBARRIER_WAIT_PARITY(mbar_smem_addr, phase_parity) do { \
    uint32_t _mbar = (uint32_t)(mbar_smem_addr); \
    uint32_t _parity = (uint32_t)(phase_parity); \
    uint32_t _done; \
    asm volatile( \
        "{\n\t.reg .pred p;\n\t" \
        "mbarrier.try_wait.parity.acquire.cta.shared::cta.b64 p, [%1], %2;\n\t" \
        "selp.b32 %0, 1, 0, p;\n\t}" \
        : "=r"(_done) : "r"(_mbar), "r"(_parity) : "memory"); \
    if (!_done) { \
        asm volatile( \
            "{\n\t.reg .pred P1;\n\t" \
            "WAIT_LOOP_%=:\n\t" \
            "mbarrier.try_wait.parity.acquire.cta.shared::cta.b64 P1, [%0], %1, 0x989680;\n\t" \
            "@P1 bra.uni WAIT_DONE_%=;\n\t" \
            "bra.uni WAIT_LOOP_%=;\n\t" \
            "WAIT_DONE_%=:\n\t}" \
            :: "r"(_mbar), "r"(_parity) : "memory"); \
    } \
} while(0)

#define TCGEN05_ALLOC(smem_result_addr, nCols) \
    asm volatile("tcgen05.alloc.cta_group::1.sync.aligned.shared::cta.b32 [%0], %1;" \
        :: "r"((uint32_t)(smem_result_addr)), "r"((uint32_t)(nCols)) : "memory")
#define TCGEN05_DEALLOC(tmem_addr, nCols) \
    asm volatile("tcgen05.dealloc.cta_group::1.sync.aligned.b32 %0, %1;" \
        :: "r"(tmem_addr), "r"((uint32_t)(nCols)))
#define TCGEN05_RELINQUISH() \
    asm volatile("tcgen05.relinquish_alloc_permit.cta_group::1.sync.aligned;")
#define TCGEN05_COMMIT(mbar_smem_addr) \
    asm volatile("tcgen05.commit.cta_group::1.mbarrier::arrive::one.shared::cluster.b64 [%0];" \
        :: "r"((uint32_t)(mbar_smem_addr)) : "memory")
#define TCGEN05_WAIT_LD() \
    asm volatile("tcgen05.wait::ld.sync.aligned;" ::: "memory")
#define TCGEN05_FENCE_AFTER() \
    asm volatile("tcgen05.fence::after_thread_sync;" ::: "memory")
#define FENCE_ASYNC_SHARED() \
    asm volatile("fence.proxy.async.shared::cta;" ::: "memory")

#define TCGEN05_LD_32X32B_X32(r, tmem_addr) \
    asm volatile( \
        "tcgen05.ld.sync.aligned.32x32b.x32.b32 " \
        "{%0, %1, %2, %3, %4, %5, %6, %7, " \
        " %8, %9, %10, %11, %12, %13, %14, %15, " \
        " %16, %17, %18, %19, %20, %21, %22, %23, " \
        " %24, %25, %26, %27, %28, %29, %30, %31}, [%32];" \
        : "=r"((r)[0]),  "=r"((r)[1]),  "=r"((r)[2]),  "=r"((r)[3]), \
          "=r"((r)[4]),  "=r"((r)[5]),  "=r"((r)[6]),  "=r"((r)[7]), \
          "=r"((r)[8]),  "=r"((r)[9]),  "=r"((r)[10]), "=r"((r)[11]), \
          "=r"((r)[12]), "=r"((r)[13]), "=r"((r)[14]), "=r"((r)[15]), \
          "=r"((r)[16]), "=r"((r)[17]), "=r"((r)[18]), "=r"((r)[19]), \
          "=r"((r)[20]), "=r"((r)[21]), "=r"((r)[22]), "=r"((r)[23]), \
          "=r"((r)[24]), "=r"((r)[25]), "=r"((r)[26]), "=r"((r)[27]), \
          "=r"((r)[28]), "=r"((r)[29]), "=r"((r)[30]), "=r"((r)[31]) \
        : "r"(tmem_addr))

// SW128 K-major smem descriptor base: layout=SW128, version=1, SBO=64, LBO=1
static constexpr uint64_t SMEM_DESC_BASE_SW128 =
    (uint64_t(2)  << 61) | (uint64_t(1) << 46) | (uint64_t(64) << 32) | (uint64_t(1) << 16);
#define MAKE_SMEM_DESC(base_addr) \
    (SMEM_DESC_BASE_SW128 | ((uint64_t)((base_addr) >> 4) & 0x3FFF))

// idesc: c=F32(1@4), a=TF32(2@7), b=TF32(2@10), N>>3 @17, M>>4 @24
static constexpr uint32_t IDESC_TF32 =
    (1u << 4) | (2u << 7) | (2u << 10) | ((TILE / 8) << 17) | ((TILE / 16) << 24);

__device__ __forceinline__ void mma_tf32(uint32_t d, uint64_t ad, uint64_t bd, uint32_t en) {
    asm volatile(
        "{\n\t.reg .pred p;\n\tsetp.ne.u32 p, %4, 0;\n\t"
        "tcgen05.mma.cta_group::1.kind::tf32 [%0], %1, %2, %3, {%5,%5,%5,%5}, p;\n\t}"
        :: "r"(d), "l"(ad), "l"(bd), "r"(IDESC_TF32), "r"(en), "r"(0u) : "memory");
}

// stage one 128x32 fp32 tile into hi/lo tf32-split SW128-swizzled smem tiles
// 512 threads: 2 float4 per thread per tile
__device__ __forceinline__ void stage_tile(const float* __restrict__ src, int ld,
                                           int rowbase, int k0,
                                           char* sm_hi, char* sm_lo, int tid)
{
#pragma unroll
    for (int it = 0; it < 2; ++it) {
        int f = tid + NTHR * it;
        int r = f >> 3;
        int c = f & 7;
        const float4 v = *(const float4*)(src + (size_t)(rowbase + r) * ld + k0 + c * 4);
        uint32_t off = (uint32_t)(r * 128 + c * 16);
        uint32_t sw = off ^ ((off >> 3) & 0x70);
        float4 h, l;
        h.x = __uint_as_float(__float_as_uint(v.x) & 0xFFFFE000u); l.x = v.x - h.x;
        h.y = __uint_as_float(__float_as_uint(v.y) & 0xFFFFE000u); l.y = v.y - h.y;
        h.z = __uint_as_float(__float_as_uint(v.z) & 0xFFFFE000u); l.z = v.z - h.z;
        h.w = __uint_as_float(__float_as_uint(v.w) & 0xFFFFE000u); l.w = v.w - h.w;
        *(float4*)(sm_hi + sw) = h;
        *(float4*)(sm_lo + sw) = l;
    }
}
#endif  // HAVE_TCGEN05

// ---------------- GEMM: C = A[M,K] @ Bt[N,K]^T (fp32 in/out) ----------------
// epi: 0 none, 1 relu, 2 add broadcast row g_crow
// transC: 0 -> C[row*ldc+col]; 1 -> C[col*ldc+row]
__global__ void __launch_bounds__(NTHR, 1)
gemm_any(const float* __restrict__ A, int lda,
         const float* __restrict__ Bt, int ldb,
         float* __restrict__ C, int ldc, int K, int epi, int transC)
{
    extern __shared__ char smem[];
    const int tid = threadIdx.x;
    const int col0 = blockIdx.x * TILE;
    const int row0 = blockIdx.y * TILE;

#if HAVE_TCGEN05
    // ---------------- tcgen05 3xTF32 path ----------------
    const uint32_t smem_base = smem_to_u32(smem);
    const int wid = tid >> 5;
    const int lid = tid & 31;

    if (wid == 0) TCGEN05_ALLOC(smem_base + 0, 128);
    if (tid == 0) {
        MBARRIER_INIT(smem_base + 8, 1);    // mbar for buffer 0
        MBARRIER_INIT(smem_base + 16, 1);   // mbar for buffer 1
    }
    __syncthreads();
    uint32_t tmem;
    asm volatile("ld.shared.b32 %0, [%1];" : "=r"(tmem) : "r"(smem_base));

    char* bufs = smem + SM_HDR;   // per buf: [Ahi][Alo][Bhi][Blo]

    stage_tile(A,  lda, row0, 0, bufs + 0 * TILE_BYTES, bufs + 1 * TILE_BYTES, tid);
    stage_tile(Bt, ldb, col0, 0, bufs + 2 * TILE_BYTES, bufs + 3 * TILE_BYTES, tid);
    FENCE_ASYNC_SHARED();
    __syncthreads();

    const int nch = K / BKC;
    for (int c = 0; c < nch; ++c) {
        const int buf = c & 1;
        // issue MMAs for chunk c on buffer buf; commit -> mbar[buf]
        if (wid == 0 && elect_one_pred()) {
            uint64_t ah = MAKE_SMEM_DESC(smem_base + SM_HDR + buf * BUF_BYTES);
            uint64_t al = ah + (TILE_BYTES >> 4);
            uint64_t bh = ah + 2 * (TILE_BYTES >> 4);
            uint64_t bl = ah + 3 * (TILE_BYTES >> 4);
            uint32_t en = (c > 0) ? 1u : 0u;
#pragma unroll
            for (int s = 0; s < 4; ++s) {   // 4 k-steps of 8 (32B = 2 desc units)
                mma_tf32(tmem, ah + 2 * s, bh + 2 * s, en); en = 1u;
                mma_tf32(tmem, ah + 2 * s, bl + 2 * s, 1u);
                mma_tf32(tmem, al + 2 * s, bh + 2 * s, 1u);
            }
            TCGEN05_COMMIT(smem_base + 8 + 8 * buf);
        }
        if (c + 1 < nch) {
            // buffer buf^1 was last used by chunk c-1 (its ((c-1)>>1)-th commit).
            // That mbar gets no further commits until next iteration -> no phase lap.
            if (c >= 1) MBARRIER_WAIT_PARITY(smem_base + 8 + 8 * (buf ^ 1), ((c - 1) >> 1) & 1);
            char* nb = bufs + (buf ^ 1) * BUF_BYTES;
            stage_tile(A,  lda, row0, (c + 1) * BKC, nb + 0 * TILE_BYTES, nb + 1 * TILE_BYTES, tid);
            stage_tile(Bt, ldb, col0, (c + 1) * BKC, nb + 2 * TILE_BYTES, nb + 3 * TILE_BYTES, tid);
            FENCE_ASYNC_SHARED();
        }
        __syncthreads();
    }
    // wait for the final chunk's MMA (serialized accumulator => all prior done)
    MBARRIER_WAIT_PARITY(smem_base + 8 + 8 * ((nch - 1) & 1), ((nch - 1) >> 1) & 1);
    TCGEN05_FENCE_AFTER();

    // epilogue: warps 0-3 (wg0) handle col groups 0,1; warps 4-7 (wg1) groups 2,3
    if (wid < 8) {
        const int wg = wid >> 2;
        const int row = row0 + (wid & 3) * 32 + lid;
#pragma unroll
        for (int gg = 0; gg < 2; ++gg) {
            const int g = wg * 2 + gg;
            uint32_t r[32];
            TCGEN05_LD_32X32B_X32(r, tmem + g * 32);
            TCGEN05_WAIT_LD();
            if (!transC) {
#pragma unroll
                for (int j = 0; j < 32; j += 4) {
                    const int col = col0 + g * 32 + j;
                    float4 v;
                    v.x = __uint_as_float(r[j + 0]);
                    v.y = __uint_as_float(r[j + 1]);
                    v.z = __uint_as_float(r[j + 2]);
                    v.w = __uint_as_float(r[j + 3]);
                    if (epi == 1) {
                        v.x = fmaxf(v.x, 0.0f); v.y = fmaxf(v.y, 0.0f);
                        v.z = fmaxf(v.z, 0.0f); v.w = fmaxf(v.w, 0.0f);
                    } else if (epi == 2) {
                        v.x += g_crow[col + 0]; v.y += g_crow[col + 1];
                        v.z += g_crow[col + 2]; v.w += g_crow[col + 3];
                    }
                    *(float4*)(C + (size_t)row * ldc + col) = v;
                }
            } else {
#pragma unroll
                for (int j = 0; j < 32; ++j) {
                    const int col = col0 + g * 32 + j;
                    C[(size_t)col * ldc + row] = __uint_as_float(r[j]);
                }
            }
        }
    }
    __syncthreads();
    if (tid == 0) {
        asm volatile("mbarrier.inval.shared.b64 [%0];" :: "r"(smem_base + 8) : "memory");
        asm volatile("mbarrier.inval.shared.b64 [%0];" :: "r"(smem_base + 16) : "memory");
    }
    __syncthreads();
    if (wid == 0) {
        TCGEN05_RELINQUISH();
        TCGEN05_DEALLOC(tmem, 128);
    }

#else
    // ---------------- FFMA fallback (compile-only on non-103a passes) -------
    if (tid < 256) {
        const int BKT = 16, TT = 8;
        float* As = (float*)smem;             // [16][132]
        float* Bs = As + BKT * (TILE + 4);    // [16][132]
        const int tx = tid & 15;   // along N
        const int ty = tid >> 4;   // along M

        float4 aPre[2], bPre[2];
        float acc[8][8];
#pragma unroll
        for (int i = 0; i < TT; i++)
#pragma unroll
            for (int j = 0; j < TT; j++) acc[i][j] = 0.0f;

        auto loadA = [&](int k0, float4* dst) {
#pragma unroll
            for (int r = 0; r < 2; r++) {
                int f = tid + 256 * r;
                int ar = f >> 2;
                int ak = (f & 3) * 4;
                dst[r] = *(const float4*)(A + (size_t)(row0 + ar) * lda + k0 + ak);
            }
        };
        auto loadB = [&](int k0, float4* dst) {
#pragma unroll
            for (int r = 0; r < 2; r++) {
                int f = tid + 256 * r;
                int bn = f >> 2;
                int bk = (f & 3) * 4;
                dst[r] = *(const float4*)(Bt + (size_t)(col0 + bn) * ldb + k0 + bk);
            }
        };
        auto storeA = [&](const float4* src) {
#pragma unroll
            for (int r = 0; r < 2; r++) {
                int f = tid + 256 * r;
                int ar = f >> 2;
                int ak = (f & 3) * 4;
                As[(ak + 0) * (TILE + 4) + ar] = src[r].x;
                As[(ak + 1) * (TILE + 4) + ar] = src[r].y;
                As[(ak + 2) * (TILE + 4) + ar] = src[r].z;
                As[(ak + 3) * (TILE + 4) + ar] = src[r].w;
            }
        };
        auto storeB = [&](const float4* src) {
#pragma unroll
            for (int r = 0; r < 2; r++) {
                int f = tid + 256 * r;
                int bn = f >> 2;
                int bk = (f & 3) * 4;
                Bs[(bk + 0) * (TILE + 4) + bn] = src[r].x;
                Bs[(bk + 1) * (TILE + 4) + bn] = src[r].y;
                Bs[(bk + 2) * (TILE + 4) + bn] = src[r].z;
                Bs[(bk + 3) * (TILE + 4) + bn] = src[r].w;
            }
        };

        loadA(0, aPre);
        loadB(0, bPre);
        storeA(aPre);
        storeB(bPre);
        __syncthreads();

        for (int k0 = BKT; k0 <= K; k0 += BKT) {
            const bool more = (k0 < K);
            if (more) { loadA(k0, aPre); loadB(k0, bPre); }
#pragma unroll
            for (int k = 0; k < BKT; k++) {
                float a[8], b[8];
#pragma unroll
                for (int i = 0; i < TT; i++) a[i] = As[k * (TILE + 4) + ty * TT + i];
#pragma unroll
                for (int j = 0; j < TT; j++) b[j] = Bs[k * (TILE + 4) + tx * TT + j];
#pragma unroll
                for (int i = 0; i < TT; i++)
#pragma unroll
                    for (int j = 0; j < TT; j++)
                        acc[i][j] = fmaf(a[i], b[j], acc[i][j]);
            }
            __syncthreads();
            if (more) {
                storeA(aPre);
                storeB(bPre);
                __syncthreads();
            }
        }

#pragma unroll
        for (int i = 0; i < TT; i++) {
            const int row = row0 + ty * TT + i;
#pragma unroll
            for (int j = 0; j < TT; j += 4) {
                const int col = col0 + tx * TT + j;
                float4 v = make_float4(acc[i][j], acc[i][j + 1], acc[i][j + 2], acc[i][j + 3]);
                if (epi == 1) {
                    v.x = fmaxf(v.x, 0.0f); v.y = fmaxf(v.y, 0.0f);
                    v.z = fmaxf(v.z, 0.0f); v.w = fmaxf(v.w, 0.0f);
                } else if (epi == 2) {
                    v.x += g_crow[col + 0]; v.y += g_crow[col + 1];
                    v.z += g_crow[col + 2]; v.w += g_crow[col + 3];
                }
                if (!transC) {
                    *(float4*)(C + (size_t)row * ldc + col) = v;
                } else {
                    C[(size_t)(col + 0) * ldc + row] = v.x;
                    C[(size_t)(col + 1) * ldc + row] = v.y;
                    C[(size_t)(col + 2) * ldc + row] = v.z;
                    C[(size_t)(col + 3) * ldc + row] = v.w;
                }
            }
        }
    }
#endif
}

// ---------------- small transpose / elementwise kernels ---------------------
__global__ void k_w1t(const float* __restrict__ W1, float* __restrict__ W1t) {
    int idx = blockIdx.x * blockDim.x + threadIdx.x;
    if (idx >= H1D * F_IN) return;
    int n = idx / F_IN, k = idx % F_IN;
    W1t[idx] = W1[k * H1D + n];
}
__global__ void k_wcatt(const float* __restrict__ W2, const float* __restrict__ W3,
                        const float* __restrict__ W4, const float* __restrict__ W5,
                        float* __restrict__ Wcatt) {
    int idx = blockIdx.x * blockDim.x + threadIdx.x;
    if (idx >= WCATN * H1D) return;
    int n = idx / H1D, k = idx % H1D;
    int sel = n >> 7, nn = n & (H2D - 1);
    const float* W = (sel == 0) ? W2 : (sel == 1) ? W3 : (sel == 2) ? W4 : W5;
    Wcatt[idx] = W[k * H2D + nn];
}
__global__ void k_wlt(const float* __restrict__ Wl, float* __restrict__ Wlt) {
    int idx = blockIdx.x * blockDim.x + threadIdx.x;
    if (idx >= H2D * H2D) return;
    int n = idx / H2D, k = idx % H2D;
    Wlt[idx] = Wl[k * H2D + n];  // top half of Wl
}

__global__ void k_z(const float* __restrict__ Mb, const float* __restrict__ eps_z,
                    float* __restrict__ out_z, float* __restrict__ out_mu,
                    float* __restrict__ out_lv) {
    int idx = blockIdx.x * blockDim.x + threadIdx.x;
    if (idx >= NN * H2D) return;
    int i = idx >> 7, j = idx & (H2D - 1);
    float mu = Mb[i * WCATN + j];
    float lv = Mb[i * WCATN + H2D + j];
    out_mu[idx] = mu;
    out_lv[idx] = lv;
    out_z[idx] = eps_z[idx] * expf(lv) + mu;
}

__global__ void k_reduce(const float* __restrict__ Mb) {
    __shared__ float s1[256];
    __shared__ float s2[256];
    int j = blockIdx.x, t = threadIdx.x;
    float a = 0.0f, b = 0.0f;
    for (int i = t; i < NN; i += 256) {
        float cm = Mb[i * WCATN + 2 * H2D + j];
        float cl = Mb[i * WCATN + 3 * H2D + j];
        float var = expf(cl);
        if (var == 0.0f) var = 1e-6f;
        float inv = 1.0f / var;
        a += inv;
        b += cm * inv;
    }
    s1[t] = a; s2[t] = b;
    __syncthreads();
    for (int s = 128; s > 0; s >>= 1) {
        if (t < s) { s1[t] += s1[t + s]; s2[t] += s2[t + s]; }
        __syncthreads();
    }
    if (t == 0) { g_prec[j] = s1[0]; g_wmu[j] = s2[0]; }
}

__global__ void k_final(const float* __restrict__ eps_g, const float* __restrict__ Wl,
                        const float* __restrict__ bl) {
    __shared__ float cl_sh[H2D];
    int j = threadIdx.x;
    float gvar = 1.0f / g_prec[j];
    float gmu = gvar * g_wmu[j];
    float gv = (gvar == 0.0f) ? 1e-6f : gvar;
    float glv = logf(gv);
    float cl = gmu + expf(0.5f * glv) * eps_g[j];
    g_gmu[j] = gmu;
    g_glv[j] = glv;
    cl_sh[j] = cl;
    __syncthreads();
    float s = bl[j];
#pragma unroll 8
    for (int k = 0; k < H2D; k++)
        s = fmaf(cl_sh[k], Wl[(H2D + k) * H2D + j], s);
    g_crow[j] = s;
}

__global__ void k_bcast(float* __restrict__ out_gmu, float* __restrict__ out_glv) {
    int idx = blockIdx.x * blockDim.x + threadIdx.x;
    if (idx >= NN * H2D) return;
    int j = idx & (H2D - 1);
    out_gmu[idx] = g_gmu[j];
    out_glv[idx] = g_glv[j];
}

// ---------------- launch ----------------------------------------------------
extern "C" void kernel_launch(void* const* d_in, const int* in_sizes, int n_in,
                              void* d_out, int out_size)
{
    const float* x     = (const float*)d_in[0];
    const float* adj   = (const float*)d_in[1];
    const float* W1    = (const float*)d_in[2];
    const float* W2    = (const float*)d_in[3];
    const float* W3    = (const float*)d_in[4];
    const float* W4    = (const float*)d_in[5];
    const float* W5    = (const float*)d_in[6];
    const float* Wl    = (const float*)d_in[7];
    const float* bl    = (const float*)d_in[8];
    const float* eps_z = (const float*)d_in[9];
    const float* eps_g = (const float*)d_in[10];

    float* out = (float*)d_out;
    float* out_recon = out;
    float* out_z     = out + (size_t)NN * NN;
    float* out_mu    = out_z  + (size_t)NN * H2D;
    float* out_lv    = out_mu + (size_t)NN * H2D;
    float* out_gmu   = out_lv + (size_t)NN * H2D;
    float* out_glv   = out_gmu + (size_t)NN * H2D;

    float *T0t, *h1, *W1t, *Wcatt, *T1t, *Mb, *Wlt, *uz;
    cudaGetSymbolAddress((void**)&T0t,   g_T0t);
    cudaGetSymbolAddress((void**)&h1,    g_h1);
    cudaGetSymbolAddress((void**)&W1t,   g_W1t);
    cudaGetSymbolAddress((void**)&Wcatt, g_Wcatt);
    cudaGetSymbolAddress((void**)&T1t,   g_T1t);
    cudaGetSymbolAddress((void**)&Mb,    g_Mb);
    cudaGetSymbolAddress((void**)&Wlt,   g_Wlt);
    cudaGetSymbolAddress((void**)&uz,    g_uz);

    cudaFuncSetAttribute(gemm_any, cudaFuncAttributeMaxDynamicSharedMemorySize, SMEM_TOT);

    // weight transposes (small)
    k_w1t  <<<(H1D * F_IN + 255) / 256, 256>>>(W1, W1t);
    k_wcatt<<<(WCATN * H1D + 255) / 256, 256>>>(W2, W3, W4, W5, Wcatt);
    k_wlt  <<<(H2D * H2D + 255) / 256, 256>>>(Wl, Wlt);

    // G1: T0t = (x @ W1)^T        M=8192 N=256 K=512
    gemm_any<<<dim3(H1D / TILE, NN / TILE), NTHR, SMEM_TOT>>>(x, F_IN, W1t, F_IN, T0t, NN, F_IN, 0, 1);
    // G2: h1 = relu(adj @ T0)     M=8192 N=256 K=8192
    gemm_any<<<dim3(H1D / TILE, NN / TILE), NTHR, SMEM_TOT>>>(adj, NN, T0t, NN, h1, H1D, NN, 1, 0);
    // G3: T1t = (h1 @ Wcat)^T     M=8192 N=512 K=256
    gemm_any<<<dim3(WCATN / TILE, NN / TILE), NTHR, SMEM_TOT>>>(h1, H1D, Wcatt, H1D, T1t, NN, H1D, 0, 1);
    // G4: Mb = adj @ T1           M=8192 N=512 K=8192
    gemm_any<<<dim3(WCATN / TILE, NN / TILE), NTHR, SMEM_TOT>>>(adj, NN, T1t, NN, Mb, WCATN, NN, 0, 0);

    // z / mu / logvar + group evidence
    k_z     <<<(NN * H2D + 255) / 256, 256>>>(Mb, eps_z, out_z, out_mu, out_lv);
    k_reduce<<<H2D, 256>>>(Mb);
    k_final <<<1, H2D>>>(eps_g, Wl, bl);
    k_bcast <<<(NN * H2D + 255) / 256, 256>>>(out_gmu, out_glv);

    // G5: uz = z @ Wl_top + crow  M=8192 N=128 K=128
    gemm_any<<<dim3(1, NN / TILE), NTHR, SMEM_TOT>>>(out_z, H2D, Wlt, H2D, uz, H2D, H2D, 2, 0);
    // G6: recon = uz @ uz^T       M=8192 N=8192 K=128
    gemm_any<<<dim3(NN / TILE, NN / TILE), NTHR, SMEM_TOT>>>(uz, H2D, uz, H2D, out_recon, NN, H2D, 0, 0);
}